// round 14
// baseline (speedup 1.0000x reference)
#include <cuda_runtime.h>
#include <cuda_bf16.h>
#include <math.h>
#include <stdint.h>

// ---------------------------------------------------------------------------
// Problem constants (N=1, S=4, AN=5 -> an2=25, D=8, H=W=48, PSV_RANGE=4)
// ---------------------------------------------------------------------------
#define HW 48
#define NPX (HW * HW)          // 2304

// Ping-pong scratch: max tensor is pp2 output [200, 64, 48, 48]
__device__ float g_bufA[200 * 64 * NPX];
__device__ float g_bufB[200 * 64 * NPX];
__device__ float g_wT[640000];   // transposed weights, all conv layers

// ---------------------------------------------------------------------------
// Packed-fp32 + async-copy helpers
// ---------------------------------------------------------------------------
__device__ __forceinline__ uint32_t smem_u32(const void* p) {
    uint32_t a;
    asm("{ .reg .u64 t; cvta.to.shared.u64 t, %1; cvt.u32.u64 %0, t; }"
        : "=r"(a) : "l"(p));
    return a;
}
__device__ __forceinline__ void lds128v2(uint32_t addr,
                                         unsigned long long& a, unsigned long long& b) {
    asm volatile("ld.shared.v2.b64 {%0, %1}, [%2];" : "=l"(a), "=l"(b) : "r"(addr));
}
__device__ __forceinline__ unsigned long long bcast2(float v) {
    unsigned long long r;
    asm("mov.b64 %0, {%1, %1};" : "=l"(r) : "f"(v));
    return r;
}
__device__ __forceinline__ void ffma2(unsigned long long& d,
                                      unsigned long long a, unsigned long long b) {
    asm("fma.rn.f32x2 %0, %1, %2, %0;" : "+l"(d) : "l"(a), "l"(b));
}
__device__ __forceinline__ void unpack2(unsigned long long p, float& lo, float& hi) {
    asm("mov.b64 {%0, %1}, %2;" : "=f"(lo), "=f"(hi) : "l"(p));
}
__device__ __forceinline__ void cp_async8(uint32_t dst, const void* src) {
    asm volatile("cp.async.ca.shared.global [%0], [%1], 8;" :: "r"(dst), "l"(src));
}
__device__ __forceinline__ void cp_async16(uint32_t dst, const void* src) {
    asm volatile("cp.async.ca.shared.global [%0], [%1], 16;" :: "r"(dst), "l"(src));
}
__device__ __forceinline__ void cp_commit() {
    asm volatile("cp.async.commit_group;");
}
__device__ __forceinline__ void cp_wait0() {
    asm volatile("cp.async.wait_group 0;");
}

// ---------------------------------------------------------------------------
// Weight transpose: [Cout][Cin][KK] -> [Cin*KK][Cout] per layer (g_wT offsets)
// ---------------------------------------------------------------------------
__global__ void wtransAll(const float* w0, const float* w1, const float* w2,
                          const float* w3, const float* w4, const float* w5,
                          const float* w6, const float* w7, const float* w8,
                          const float* w9, float* out) {
    int L = blockIdx.y;
    const float* w; int Cout, Cin, KK, off;
    switch (L) {
        case 0: w = w0; Cout = 32;  Cin = 4;   KK = 25; off = 0;      break;
        case 1: w = w1; Cout = 64;  Cin = 32;  KK = 25; off = 3200;   break;
        case 2: w = w2; Cout = 32;  Cin = 64;  KK = 25; off = 54400;  break;
        case 3: w = w3; Cout = 4;   Cin = 32;  KK = 25; off = 105600; break;
        case 4: w = w4; Cout = 200; Cin = 32;  KK = 9;  off = 108800; break;
        case 5: w = w5; Cout = 200; Cin = 200; KK = 9;  off = 166400; break;
        case 6: w = w6; Cout = 8;   Cin = 200; KK = 25; off = 526400; break;
        case 7: w = w7; Cout = 64;  Cin = 8;   KK = 25; off = 566400; break;
        case 8: w = w8; Cout = 32;  Cin = 64;  KK = 25; off = 579200; break;
        default: w = w9; Cout = 16; Cin = 32;  KK = 9;  off = 630400; break;
    }
    int n = Cout * Cin * KK;
    int ck = Cin * KK;
    for (int idx = blockIdx.x * 256 + threadIdx.x; idx < n; idx += gridDim.x * 256) {
        int o = idx / ck, rm = idx % ck;
        int c = rm / KK, k = rm % KK;
        out[off + (c * KK + k) * Cout + o] = w[idx];
    }
}

// ---------------------------------------------------------------------------
// Bilinear sampling identical to reference grid_sample(align_corners=False,
// padding=zeros):  ix = (X+off)*48/47 - 0.5
// ---------------------------------------------------------------------------
__device__ __forceinline__ float tap48(const float* __restrict__ im, int x, int y) {
    return (x >= 0 && x < HW && y >= 0 && y < HW) ? im[y * HW + x] : 0.0f;
}

__device__ __forceinline__ float bilin48(const float* __restrict__ im, float ix, float iy) {
    float x0f = floorf(ix), y0f = floorf(iy);
    int   x0  = (int)x0f,   y0  = (int)y0f;
    float wx = ix - x0f, wy = iy - y0f;
    float v00 = tap48(im, x0,     y0);
    float v01 = tap48(im, x0 + 1, y0);
    float v10 = tap48(im, x0,     y0 + 1);
    float v11 = tap48(im, x0 + 1, y0 + 1);
    return (1.0f - wy) * ((1.0f - wx) * v00 + wx * v01) +
           wy          * ((1.0f - wx) * v10 + wx * v11);
}

// ---------------------------------------------------------------------------
// PSV build: 800 blocks, one per (t,d,s) tuple. Output [td(200), s(4), 2304].
// ---------------------------------------------------------------------------
__global__ void psv_kernel(const float* __restrict__ img, const int* __restrict__ ind,
                           float* __restrict__ out) {
    int k  = blockIdx.x;     // k = (t*8+d)*4 + s
    int s  = k & 3;
    int td = k >> 2;
    int d  = td & 7;
    int t  = td >> 3;
    float t_h = (float)(t / 5), t_w = (float)(t % 5);
    int   is  = ind[s];
    float s_h = (float)(is / 5), s_w = (float)(is % 5);
    float disp = -4.0f + (float)d * (8.0f / 7.0f);  // linspace(-4,4,8)
    float offw = disp * (t_w - s_w);
    float offh = disp * (t_h - s_h);
    const float* im = img + s * NPX;
    float* op = out + (td * 4 + s) * NPX;
    const float sc = 48.0f / 47.0f;
    for (int p = threadIdx.x; p < NPX; p += blockDim.x) {
        int y = p / HW, x = p % HW;
        float ix = ((float)x + offw) * sc - 0.5f;
        float iy = ((float)y + offh) * sc - 0.5f;
        op[p] = bilin48(im, ix, iy);
    }
}

// ---------------------------------------------------------------------------
// Packed-f32x2 direct conv, cp.async pipeline over CHANNEL PAIRS.
//  - PXB=4 / 192-thread blocks: smaller acc (32 regs) -> >=4 blocks/SM,
//    768+ threads/SM (occ 37%+) vs 640 previously.
//  - tile AND weights both arrive via cp.async (weights from the transposed
//    [cin][tap][oc] copy) -> no register staging, no STS in the mainloop.
//  - padded tile [(ROWS+4) x 52], interior at (2,2); halos zeroed once.
//  - weight fragment = ld.shared.v2.b64 (one LDS.128 -> two f32x2 operands).
//  - per ky: bcast-pack the (K+PXB-1)-value pixel row once, reuse across kx.
// CIN must be even. SPLITS>1: split-K over input channels, raw partials,
// blockIdx.x = slice*nb + b; reduceK combines slices deterministically.
// ---------------------------------------------------------------------------
template <int K, int ROWS, int PXB, int OCB, int CIN, int SPLITS, bool RELU>
__global__ void __launch_bounds__(ROWS * HW / PXB, 4)
convp(const float* __restrict__ in, const float* __restrict__ wtT,
      const float* __restrict__ bias, float* __restrict__ out,
      int Cout, int nb) {
    static_assert(CIN % 2 == 0, "CIN must be even");
    static_assert(OCB % 4 == 0 || OCB == 4, "OCB pairs");
    constexpr int KK   = K * K;
    constexpr int PAD  = K / 2;
    constexpr int TWP  = 52;               // padded width
    constexpr int THP  = ROWS + 4;         // padded height
    constexpr int TTP  = THP * TWP;
    constexpr int NTHR = ROWS * HW / PXB;
    constexpr int RPT  = HW / PXB;
    constexpr int OC2  = OCB / 2;
    constexpr int WCH  = KK * OCB;
    constexpr int WCHK = 2 * WCH / 4;      // 16B chunks per channel pair
    constexpr int NWL  = (WCHK + NTHR - 1) / NTHR;
    constexpr int NCH  = THP * 24;         // 8B chunks per channel fill
    constexpr int NCPA = (NCH + NTHR - 1) / NTHR;
    constexpr int VN   = K + PXB - 1;
    constexpr int NPAIR = CIN / 2;
    constexpr int CINTOT = CIN * SPLITS;

    __shared__ __align__(16) float s_in[2][2 * TTP];   // [slot][2 channels]
    __shared__ __align__(16) float s_w[2][2 * WCH];

    const int tid    = threadIdx.x;
    const int bIn    = blockIdx.x % nb;
    const int slice  = blockIdx.x / nb;
    const int ocBase = blockIdx.y * OCB;
    const int row0   = blockIdx.z * ROWS;
    const int cin0   = slice * CIN;

    const int r    = tid / RPT;
    const int col0 = (tid % RPT) * PXB;
    const float* inB = in + ((size_t)bIn * CINTOT + cin0) * NPX;

    const uint32_t sinAddr = smem_u32(&s_in[0][0]);
    const uint32_t wbase   = smem_u32(&s_w[0][0]);

    // ---- zero all tile buffers (halos/OOB rows stay zero forever) ----
    for (int i = tid; i < 4 * TTP; i += NTHR) (&s_in[0][0])[i] = 0.0f;
    __syncthreads();

    // ---- fill one channel's tile interior via cp.async (8B chunks) ----
    auto fill1 = [&](int ch, uint32_t dstB) {
        const float* ip = inB + (size_t)ch * NPX;
#pragma unroll
        for (int l = 0; l < NCPA; l++) {
            int idx = tid + l * NTHR;
            if (idx < NCH) {
                int ty = idx / 24, chk = idx % 24;
                int gy = row0 + ty - 2;
                if (gy >= 0 && gy < HW)
                    cp_async8(dstB + (uint32_t)((ty * TWP + 2 + chk * 2) * 4),
                              ip + gy * HW + chk * 2);
            }
        }
    };
    auto fillPair = [&](int pair, int slot) {
        uint32_t base = sinAddr + (uint32_t)(slot * 2 * TTP) * 4u;
        fill1(2 * pair,     base);
        fill1(2 * pair + 1, base + (uint32_t)TTP * 4u);
    };
    // ---- weights for a channel pair via 16B cp.async from transposed copy
    auto fillW = [&](int pair, int slot) {
#pragma unroll
        for (int l = 0; l < NWL; l++) {
            int idx = tid + l * NTHR;
            if (idx < WCHK) {
                int q  = idx * 4;            // float offset in [c][kk][oc]
                int c  = q / WCH;
                int rm = q % WCH;
                int kk = rm / OCB;
                int oo = rm % OCB;
                const float* src = wtT +
                    ((size_t)(cin0 + 2 * pair + c) * KK + kk) * Cout + ocBase + oo;
                cp_async16(wbase + (uint32_t)((slot * 2 * WCH + q) * 4), src);
            }
        }
    };

    // ---- prestage pair 0 ----
    fillPair(0, 0);
    fillW(0, 0);
    cp_commit();
    cp_wait0();
    __syncthreads();

    unsigned long long acc[OC2][PXB];
#pragma unroll
    for (int o2 = 0; o2 < OC2; o2++)
#pragma unroll
        for (int j = 0; j < PXB; j++) acc[o2][j] = 0ULL;

#pragma unroll 1
    for (int p2 = 0; p2 < NPAIR; p2++) {
        const int slot = p2 & 1;
        if (p2 + 1 < NPAIR) {
            fillPair(p2 + 1, slot ^ 1);
            fillW(p2 + 1, slot ^ 1);
            cp_commit();
        }

        // compute both channels of this pair
#pragma unroll
        for (int sub = 0; sub < 2; sub++) {
            const float* pv = &s_in[slot][sub * TTP + (r + 2 - PAD) * TWP + col0 + 2 - PAD];
            const uint32_t wb = wbase + (uint32_t)((slot * 2 * WCH + sub * WCH) * 4);
#pragma unroll
            for (int ky = 0; ky < K; ky++) {
                unsigned long long vb[VN];
#pragma unroll
                for (int i = 0; i < VN; i++) vb[i] = bcast2(pv[ky * TWP + i]);
#pragma unroll
                for (int kx = 0; kx < K; kx++) {
                    unsigned long long w2[OC2];
#pragma unroll
                    for (int o2 = 0; o2 < OC2; o2 += 2)
                        lds128v2(wb + (uint32_t)(((ky * K + kx) * OCB + 2 * o2) * 4),
                                 w2[o2], w2[o2 + 1]);
#pragma unroll
                    for (int j = 0; j < PXB; j++)
#pragma unroll
                        for (int o2 = 0; o2 < OC2; o2++)
                            ffma2(acc[o2][j], w2[o2], vb[kx + j]);
                }
            }
        }

        if (p2 + 1 < NPAIR) cp_wait0();
        __syncthreads();
    }

    // ---- epilogue: unpack pairs, bias, relu, store ----
#pragma unroll
    for (int o2 = 0; o2 < OC2; o2++) {
        int oc0 = ocBase + 2 * o2;
        float b0 = (SPLITS == 1) ? bias[oc0]     : 0.0f;
        float b1 = (SPLITS == 1) ? bias[oc0 + 1] : 0.0f;
        float* op0 = out + ((size_t)blockIdx.x * Cout + oc0) * NPX + (row0 + r) * HW + col0;
        float* op1 = op0 + NPX;
#pragma unroll
        for (int j = 0; j < PXB; j++) {
            float lo, hi;
            unpack2(acc[o2][j], lo, hi);
            lo += b0; hi += b1;
            if (RELU) { lo = fmaxf(lo, 0.0f); hi = fmaxf(hi, 0.0f); }
            op0[j] = lo;
            op1[j] = hi;
        }
    }
}

// ---------------------------------------------------------------------------
// Scalar conv (kept only for dp4: 5 output channels). Runtime Cin, raw weights.
// ---------------------------------------------------------------------------
template <int K, int ROWS, int PXB, int OCB, bool RELU>
__global__ void __launch_bounds__(ROWS * HW / PXB)
conv2(const float* __restrict__ in, const float* __restrict__ wt,
      const float* __restrict__ bias, float* __restrict__ out,
      int Cin, int Cout, int nb) {
    constexpr int KK   = K * K;
    constexpr int PAD  = K / 2;
    constexpr int TW   = HW + K - 1;
    constexpr int TH   = ROWS + K - 1;
    constexpr int NTHR = ROWS * HW / PXB;
    constexpr int RPT  = HW / PXB;

    __shared__ float s_in[TH * TW];
    __shared__ float s_w[KK * OCB];

    const int tid    = threadIdx.x;
    const int bIn    = blockIdx.x % nb;
    const int ocBase = blockIdx.y * OCB;
    const int row0   = blockIdx.z * ROWS;

    float acc[OCB][PXB];
#pragma unroll
    for (int o = 0; o < OCB; o++)
#pragma unroll
        for (int j = 0; j < PXB; j++) acc[o][j] = 0.0f;

    const int r    = tid / RPT;
    const int col0 = (tid % RPT) * PXB;
    const float* inB = in + (size_t)bIn * Cin * NPX;

    for (int c = 0; c < Cin; c++) {
        __syncthreads();
        const float* ip = inB + (size_t)c * NPX;
        for (int idx = tid; idx < TH * TW; idx += NTHR) {
            int ty = idx / TW, tx = idx % TW;
            int gy = row0 + ty - PAD, gx = tx - PAD;
            float v = 0.0f;
            if (gy >= 0 && gy < HW && gx >= 0 && gx < HW) v = ip[gy * HW + gx];
            s_in[idx] = v;
        }
        for (int idx = tid; idx < KK * OCB; idx += NTHR) {
            int kk = idx / OCB, o = idx % OCB;
            s_w[idx] = wt[((size_t)(ocBase + o) * Cin + c) * KK + kk];
        }
        __syncthreads();

        const float* pv = s_in + r * TW + col0;
#pragma unroll
        for (int kk = 0; kk < KK; kk++) {
            const int ky = kk / K, kx = kk % K;
            float w[OCB];
#pragma unroll
            for (int o = 0; o < OCB; o++) w[o] = s_w[kk * OCB + o];
            float v[PXB];
#pragma unroll
            for (int j = 0; j < PXB; j++) v[j] = pv[ky * TW + kx + j];
#pragma unroll
            for (int o = 0; o < OCB; o++)
#pragma unroll
                for (int j = 0; j < PXB; j++)
                    acc[o][j] = fmaf(w[o], v[j], acc[o][j]);
        }
    }

#pragma unroll
    for (int o = 0; o < OCB; o++) {
        int oc = ocBase + o;
        float bv = bias[oc];
        float* op = out + ((size_t)blockIdx.x * Cout + oc) * NPX + (row0 + r) * HW + col0;
#pragma unroll
        for (int j = 0; j < PXB; j++) {
            float x = acc[o][j] + bv;
            if (RELU) x = fmaxf(x, 0.0f);
            op[j] = x;
        }
    }
}

// ---------------------------------------------------------------------------
// Generic split-K reduction: out[idx] = relu(bias[oc] + sum_s part[idx+s*tot])
// ---------------------------------------------------------------------------
template <int SPLITS>
__global__ void reduceK(const float* __restrict__ part, const float* __restrict__ bias,
                        float* __restrict__ out, int Cout, int tot) {
    int idx = blockIdx.x * 256 + threadIdx.x;
    if (idx >= tot) return;
    int oc = (idx / NPX) % Cout;
    float v = bias[oc];
#pragma unroll
    for (int s = 0; s < SPLITS; s++) v += part[idx + (size_t)s * tot];
    out[idx] = fmaxf(v, 0.0f);
}

// ---------------------------------------------------------------------------
// Final: disp out, softmax(conf), warp source views, blend.
// ---------------------------------------------------------------------------
__global__ void final_kernel(const float* __restrict__ x, const float* __restrict__ img,
                             const int* __restrict__ ind, float* __restrict__ out) {
    int t = blockIdx.x;  // 0..24
    float t_h = (float)(t / 5), t_w = (float)(t % 5);
    const float* base = x + t * 5 * NPX;
    const float sc = 48.0f / 47.0f;
    for (int p = threadIdx.x; p < NPX; p += blockDim.x) {
        float d0 = base[p];
        float l0 = base[1 * NPX + p];
        float l1 = base[2 * NPX + p];
        float l2 = base[3 * NPX + p];
        float l3 = base[4 * NPX + p];
        float m = fmaxf(fmaxf(l0, l1), fmaxf(l2, l3));
        float e0 = expf(l0 - m), e1 = expf(l1 - m), e2 = expf(l2 - m), e3 = expf(l3 - m);
        float inv = 1.0f / (e0 + e1 + e2 + e3);
        float conf[4] = {e0 * inv, e1 * inv, e2 * inv, e3 * inv};

        int y = p / HW, xx = p % HW;
        float accv = 0.0f;
#pragma unroll
        for (int s = 0; s < 4; s++) {
            int is = ind[s];
            float dw = t_w - (float)(is % 5);
            float dh = t_h - (float)(is / 5);
            float ix = ((float)xx + d0 * dw) * sc - 0.5f;
            float iy = ((float)y  + d0 * dh) * sc - 0.5f;
            accv += conf[s] * bilin48(img + s * NPX, ix, iy);
        }
        out[t * NPX + p]            = d0;    // disp_target
        out[25 * NPX + t * NPX + p] = accv;  // inter_lf
    }
}

// ---------------------------------------------------------------------------
// Launch
// ---------------------------------------------------------------------------
extern "C" void kernel_launch(void* const* d_in, const int* in_sizes, int n_in,
                              void* d_out, int out_size) {
    const float* img = (const float*)d_in[0];
    const int*   ind = (const int*)d_in[1];
    const float* pp1_w = (const float*)d_in[2];  const float* pp1_b = (const float*)d_in[3];
    const float* pp2_w = (const float*)d_in[4];  const float* pp2_b = (const float*)d_in[5];
    const float* pp3_w = (const float*)d_in[6];  const float* pp3_b = (const float*)d_in[7];
    const float* pp4_w = (const float*)d_in[8];  const float* pp4_b = (const float*)d_in[9];
    const float* cp1_w = (const float*)d_in[10]; const float* cp1_b = (const float*)d_in[11];
    const float* cp2_w = (const float*)d_in[12]; const float* cp2_b = (const float*)d_in[13];
    const float* cp3_w = (const float*)d_in[14]; const float* cp3_b = (const float*)d_in[15];
    const float* dp1_w = (const float*)d_in[16]; const float* dp1_b = (const float*)d_in[17];
    const float* dp2_w = (const float*)d_in[18]; const float* dp2_b = (const float*)d_in[19];
    const float* dp3_w = (const float*)d_in[20]; const float* dp3_b = (const float*)d_in[21];
    const float* dp4_w = (const float*)d_in[22]; const float* dp4_b = (const float*)d_in[23];

    float* bufA;  cudaGetSymbolAddress((void**)&bufA, g_bufA);
    float* bufB;  cudaGetSymbolAddress((void**)&bufB, g_bufB);
    float* wT;    cudaGetSymbolAddress((void**)&wT,   g_wT);
    float* part = bufB + (size_t)25 * 8 * NPX;   // cp3 partials (10 slices, 4.6M)

    // 0) transpose all convp weights -> g_wT ([cin][tap][oc] per layer)
    wtransAll<<<dim3(176, 10), 256>>>(pp1_w, pp2_w, pp3_w, pp4_w, cp1_w, cp2_w,
                                      cp3_w, dp1_w, dp2_w, dp3_w, wT);

    // 1) PSV sampling -> bufA [200, 4, 48, 48]
    psv_kernel<<<800, 256>>>(img, ind, bufA);

    // 2) pp chain (batch 200) — PXB=4, 192-thread blocks
    convp<5, 16, 4, 8, 4,   1, true><<<dim3(200, 4, 3), 192>>>(bufA, wT + 0,      pp1_b, bufB, 32, 200);
    convp<5, 16, 4, 8, 32,  1, true><<<dim3(200, 8, 3), 192>>>(bufB, wT + 3200,   pp2_b, bufA, 64, 200);
    convp<5, 16, 4, 8, 64,  1, true><<<dim3(200, 4, 3), 192>>>(bufA, wT + 54400,  pp3_b, bufB, 32, 200);
    convp<5, 16, 4, 4, 32,  1, true><<<dim3(200, 1, 3), 192>>>(bufB, wT + 105600, pp4_b, bufA, 4,  200);

    // bufA reinterpreted as [25, 32, 48, 48]
    // 3) cp chain (batch 25)
    convp<3, 16, 4, 8, 32,  1, true><<<dim3(25, 25, 3), 192>>>(bufA, wT + 108800, cp1_b, bufB, 200, 25);
    convp<3, 16, 4, 8, 200, 1, true><<<dim3(25, 25, 3), 192>>>(bufB, wT + 166400, cp2_b, bufA, 200, 25);
    // cp3: 200->8, split-K 10 -> grid (250,1,3) = 750 blocks
    convp<5, 16, 4, 8, 20, 10, false><<<dim3(250, 1, 3), 192>>>(bufA, wT + 526400, cp3_b, part, 8, 25);
    reduceK<10><<<25 * 8 * NPX / 256, 256>>>(part, cp3_b, bufB, 8, 25 * 8 * NPX);

    // 4) dp chain (batch 25)
    convp<5, 16, 4, 8, 8,   1, true><<<dim3(25, 8, 3), 192>>>(bufB, wT + 566400, dp1_b, bufA, 64, 25);
    convp<5, 16, 4, 8, 64,  1, true><<<dim3(25, 4, 3), 192>>>(bufA, wT + 579200, dp2_b, bufB, 32, 25);
    convp<3, 16, 4, 8, 32,  1, true><<<dim3(25, 2, 3), 192>>>(bufB, wT + 630400, dp3_b, bufA, 16, 25);
    conv2<3, 8, 6, 5, false><<<dim3(25, 1, 6), 64>>>(bufA, dp4_w, dp4_b, bufB, 16, 5, 25);

    // 5) disp + softmax-blended warp -> d_out [disp(57600) | inter_lf(57600)]
    final_kernel<<<25, 256>>>(bufB, img, ind, (float*)d_out);
}

// round 16
// speedup vs baseline: 1.0024x; 1.0024x over previous
#include <cuda_runtime.h>
#include <cuda_bf16.h>
#include <math.h>
#include <stdint.h>

// ---------------------------------------------------------------------------
// Problem constants (N=1, S=4, AN=5 -> an2=25, D=8, H=W=48, PSV_RANGE=4)
// ---------------------------------------------------------------------------
#define HW 48
#define NPX (HW * HW)          // 2304

// Ping-pong scratch: max tensor is pp2 output [200, 64, 48, 48]
__device__ float g_bufA[200 * 64 * NPX];
__device__ float g_bufB[200 * 64 * NPX];
__device__ float g_wT[640000];   // transposed weights, all conv layers

// ---------------------------------------------------------------------------
// Packed-fp32 + async-copy helpers
// ---------------------------------------------------------------------------
__device__ __forceinline__ uint32_t smem_u32(const void* p) {
    uint32_t a;
    asm("{ .reg .u64 t; cvta.to.shared.u64 t, %1; cvt.u32.u64 %0, t; }"
        : "=r"(a) : "l"(p));
    return a;
}
__device__ __forceinline__ void lds128v2(uint32_t addr,
                                         unsigned long long& a, unsigned long long& b) {
    asm volatile("ld.shared.v2.b64 {%0, %1}, [%2];" : "=l"(a), "=l"(b) : "r"(addr));
}
__device__ __forceinline__ unsigned long long bcast2(float v) {
    unsigned long long r;
    asm("mov.b64 %0, {%1, %1};" : "=l"(r) : "f"(v));
    return r;
}
__device__ __forceinline__ void ffma2(unsigned long long& d,
                                      unsigned long long a, unsigned long long b) {
    asm("fma.rn.f32x2 %0, %1, %2, %0;" : "+l"(d) : "l"(a), "l"(b));
}
__device__ __forceinline__ void unpack2(unsigned long long p, float& lo, float& hi) {
    asm("mov.b64 {%0, %1}, %2;" : "=f"(lo), "=f"(hi) : "l"(p));
}
__device__ __forceinline__ void cp_async8(uint32_t dst, const void* src) {
    asm volatile("cp.async.ca.shared.global [%0], [%1], 8;" :: "r"(dst), "l"(src));
}
__device__ __forceinline__ void cp_async16(uint32_t dst, const void* src) {
    asm volatile("cp.async.ca.shared.global [%0], [%1], 16;" :: "r"(dst), "l"(src));
}
__device__ __forceinline__ void cp_commit() {
    asm volatile("cp.async.commit_group;");
}
__device__ __forceinline__ void cp_wait0() {
    asm volatile("cp.async.wait_group 0;");
}

// ---------------------------------------------------------------------------
// Weight transpose: [Cout][Cin][KK] -> [Cin*KK][Cout] per layer (g_wT offsets)
// ---------------------------------------------------------------------------
__global__ void wtransAll(const float* w0, const float* w1, const float* w2,
                          const float* w3, const float* w4, const float* w5,
                          const float* w6, const float* w7, const float* w8,
                          const float* w9, float* out) {
    int L = blockIdx.y;
    const float* w; int Cout, Cin, KK, off;
    switch (L) {
        case 0: w = w0; Cout = 32;  Cin = 4;   KK = 25; off = 0;      break;
        case 1: w = w1; Cout = 64;  Cin = 32;  KK = 25; off = 3200;   break;
        case 2: w = w2; Cout = 32;  Cin = 64;  KK = 25; off = 54400;  break;
        case 3: w = w3; Cout = 4;   Cin = 32;  KK = 25; off = 105600; break;
        case 4: w = w4; Cout = 200; Cin = 32;  KK = 9;  off = 108800; break;
        case 5: w = w5; Cout = 200; Cin = 200; KK = 9;  off = 166400; break;
        case 6: w = w6; Cout = 8;   Cin = 200; KK = 25; off = 526400; break;
        case 7: w = w7; Cout = 64;  Cin = 8;   KK = 25; off = 566400; break;
        case 8: w = w8; Cout = 32;  Cin = 64;  KK = 25; off = 579200; break;
        default: w = w9; Cout = 16; Cin = 32;  KK = 9;  off = 630400; break;
    }
    int n = Cout * Cin * KK;
    int ck = Cin * KK;
    for (int idx = blockIdx.x * 256 + threadIdx.x; idx < n; idx += gridDim.x * 256) {
        int o = idx / ck, rm = idx % ck;
        int c = rm / KK, k = rm % KK;
        out[off + (c * KK + k) * Cout + o] = w[idx];
    }
}

// ---------------------------------------------------------------------------
// Bilinear sampling identical to reference grid_sample(align_corners=False,
// padding=zeros):  ix = (X+off)*48/47 - 0.5
// ---------------------------------------------------------------------------
__device__ __forceinline__ float tap48(const float* __restrict__ im, int x, int y) {
    return (x >= 0 && x < HW && y >= 0 && y < HW) ? im[y * HW + x] : 0.0f;
}

__device__ __forceinline__ float bilin48(const float* __restrict__ im, float ix, float iy) {
    float x0f = floorf(ix), y0f = floorf(iy);
    int   x0  = (int)x0f,   y0  = (int)y0f;
    float wx = ix - x0f, wy = iy - y0f;
    float v00 = tap48(im, x0,     y0);
    float v01 = tap48(im, x0 + 1, y0);
    float v10 = tap48(im, x0,     y0 + 1);
    float v11 = tap48(im, x0 + 1, y0 + 1);
    return (1.0f - wy) * ((1.0f - wx) * v00 + wx * v01) +
           wy          * ((1.0f - wx) * v10 + wx * v11);
}

// ---------------------------------------------------------------------------
// PSV build: 800 blocks, one per (t,d,s) tuple. Output [td(200), s(4), 2304].
// ---------------------------------------------------------------------------
__global__ void psv_kernel(const float* __restrict__ img, const int* __restrict__ ind,
                           float* __restrict__ out) {
    int k  = blockIdx.x;     // k = (t*8+d)*4 + s
    int s  = k & 3;
    int td = k >> 2;
    int d  = td & 7;
    int t  = td >> 3;
    float t_h = (float)(t / 5), t_w = (float)(t % 5);
    int   is  = ind[s];
    float s_h = (float)(is / 5), s_w = (float)(is % 5);
    float disp = -4.0f + (float)d * (8.0f / 7.0f);  // linspace(-4,4,8)
    float offw = disp * (t_w - s_w);
    float offh = disp * (t_h - s_h);
    const float* im = img + s * NPX;
    float* op = out + (td * 4 + s) * NPX;
    const float sc = 48.0f / 47.0f;
    for (int p = threadIdx.x; p < NPX; p += blockDim.x) {
        int y = p / HW, x = p % HW;
        float ix = ((float)x + offw) * sc - 0.5f;
        float iy = ((float)y + offh) * sc - 0.5f;
        op[p] = bilin48(im, ix, iy);
    }
}

// ---------------------------------------------------------------------------
// Packed-f32x2 direct conv, cp.async pipeline over CHANNEL PAIRS.
//  - PXB=4 / 192-thread blocks: smaller acc (32 regs) -> >=4 blocks/SM,
//    768+ threads/SM (occ 37%+) vs 640 previously.
//  - tile AND weights both arrive via cp.async (weights from the transposed
//    [cin][tap][oc] copy) -> no register staging, no STS in the mainloop.
//  - padded tile [(ROWS+4) x 52], interior at (2,2); halos zeroed once.
//  - weight fragment = ld.shared.v2.b64 (one LDS.128 -> two f32x2 operands).
//  - per ky: bcast-pack the (K+PXB-1)-value pixel row once, reuse across kx.
// CIN must be even. SPLITS>1: split-K over input channels, raw partials,
// blockIdx.x = slice*nb + b; reduceK combines slices deterministically.
// ---------------------------------------------------------------------------
template <int K, int ROWS, int PXB, int OCB, int CIN, int SPLITS, bool RELU>
__global__ void __launch_bounds__(ROWS * HW / PXB, 4)
convp(const float* __restrict__ in, const float* __restrict__ wtT,
      const float* __restrict__ bias, float* __restrict__ out,
      int Cout, int nb) {
    static_assert(CIN % 2 == 0, "CIN must be even");
    static_assert(OCB % 4 == 0 || OCB == 4, "OCB pairs");
    constexpr int KK   = K * K;
    constexpr int PAD  = K / 2;
    constexpr int TWP  = 52;               // padded width
    constexpr int THP  = ROWS + 4;         // padded height
    constexpr int TTP  = THP * TWP;
    constexpr int NTHR = ROWS * HW / PXB;
    constexpr int RPT  = HW / PXB;
    constexpr int OC2  = OCB / 2;
    constexpr int WCH  = KK * OCB;
    constexpr int WCHK = 2 * WCH / 4;      // 16B chunks per channel pair
    constexpr int NWL  = (WCHK + NTHR - 1) / NTHR;
    constexpr int NCH  = THP * 24;         // 8B chunks per channel fill
    constexpr int NCPA = (NCH + NTHR - 1) / NTHR;
    constexpr int VN   = K + PXB - 1;
    constexpr int NPAIR = CIN / 2;
    constexpr int CINTOT = CIN * SPLITS;

    __shared__ __align__(16) float s_in[2][2 * TTP];   // [slot][2 channels]
    __shared__ __align__(16) float s_w[2][2 * WCH];

    const int tid    = threadIdx.x;
    const int bIn    = blockIdx.x % nb;
    const int slice  = blockIdx.x / nb;
    const int ocBase = blockIdx.y * OCB;
    const int row0   = blockIdx.z * ROWS;
    const int cin0   = slice * CIN;

    const int r    = tid / RPT;
    const int col0 = (tid % RPT) * PXB;
    const float* inB = in + ((size_t)bIn * CINTOT + cin0) * NPX;

    const uint32_t sinAddr = smem_u32(&s_in[0][0]);
    const uint32_t wbase   = smem_u32(&s_w[0][0]);

    // ---- zero all tile buffers (halos/OOB rows stay zero forever) ----
    for (int i = tid; i < 4 * TTP; i += NTHR) (&s_in[0][0])[i] = 0.0f;
    __syncthreads();

    // ---- fill one channel's tile interior via cp.async (8B chunks) ----
    auto fill1 = [&](int ch, uint32_t dstB) {
        const float* ip = inB + (size_t)ch * NPX;
#pragma unroll
        for (int l = 0; l < NCPA; l++) {
            int idx = tid + l * NTHR;
            if (idx < NCH) {
                int ty = idx / 24, chk = idx % 24;
                int gy = row0 + ty - 2;
                if (gy >= 0 && gy < HW)
                    cp_async8(dstB + (uint32_t)((ty * TWP + 2 + chk * 2) * 4),
                              ip + gy * HW + chk * 2);
            }
        }
    };
    auto fillPair = [&](int pair, int slot) {
        uint32_t base = sinAddr + (uint32_t)(slot * 2 * TTP) * 4u;
        fill1(2 * pair,     base);
        fill1(2 * pair + 1, base + (uint32_t)TTP * 4u);
    };
    // ---- weights for a channel pair via 16B cp.async from transposed copy
    auto fillW = [&](int pair, int slot) {
#pragma unroll
        for (int l = 0; l < NWL; l++) {
            int idx = tid + l * NTHR;
            if (idx < WCHK) {
                int q  = idx * 4;            // float offset in [c][kk][oc]
                int c  = q / WCH;
                int rm = q % WCH;
                int kk = rm / OCB;
                int oo = rm % OCB;
                const float* src = wtT +
                    ((size_t)(cin0 + 2 * pair + c) * KK + kk) * Cout + ocBase + oo;
                cp_async16(wbase + (uint32_t)((slot * 2 * WCH + q) * 4), src);
            }
        }
    };

    // ---- prestage pair 0 ----
    fillPair(0, 0);
    fillW(0, 0);
    cp_commit();
    cp_wait0();
    __syncthreads();

    unsigned long long acc[OC2][PXB];
#pragma unroll
    for (int o2 = 0; o2 < OC2; o2++)
#pragma unroll
        for (int j = 0; j < PXB; j++) acc[o2][j] = 0ULL;

#pragma unroll 1
    for (int p2 = 0; p2 < NPAIR; p2++) {
        const int slot = p2 & 1;
        if (p2 + 1 < NPAIR) {
            fillPair(p2 + 1, slot ^ 1);
            fillW(p2 + 1, slot ^ 1);
            cp_commit();
        }

        // compute both channels of this pair
#pragma unroll
        for (int sub = 0; sub < 2; sub++) {
            const float* pv = &s_in[slot][sub * TTP + (r + 2 - PAD) * TWP + col0 + 2 - PAD];
            const uint32_t wb = wbase + (uint32_t)((slot * 2 * WCH + sub * WCH) * 4);
#pragma unroll
            for (int ky = 0; ky < K; ky++) {
                unsigned long long vb[VN];
#pragma unroll
                for (int i = 0; i < VN; i++) vb[i] = bcast2(pv[ky * TWP + i]);
#pragma unroll
                for (int kx = 0; kx < K; kx++) {
                    unsigned long long w2[OC2];
#pragma unroll
                    for (int o2 = 0; o2 < OC2; o2 += 2)
                        lds128v2(wb + (uint32_t)(((ky * K + kx) * OCB + 2 * o2) * 4),
                                 w2[o2], w2[o2 + 1]);
#pragma unroll
                    for (int j = 0; j < PXB; j++)
#pragma unroll
                        for (int o2 = 0; o2 < OC2; o2++)
                            ffma2(acc[o2][j], w2[o2], vb[kx + j]);
                }
            }
        }

        if (p2 + 1 < NPAIR) cp_wait0();
        __syncthreads();
    }

    // ---- epilogue: unpack pairs, bias, relu, store ----
#pragma unroll
    for (int o2 = 0; o2 < OC2; o2++) {
        int oc0 = ocBase + 2 * o2;
        float b0 = (SPLITS == 1) ? bias[oc0]     : 0.0f;
        float b1 = (SPLITS == 1) ? bias[oc0 + 1] : 0.0f;
        float* op0 = out + ((size_t)blockIdx.x * Cout + oc0) * NPX + (row0 + r) * HW + col0;
        float* op1 = op0 + NPX;
#pragma unroll
        for (int j = 0; j < PXB; j++) {
            float lo, hi;
            unpack2(acc[o2][j], lo, hi);
            lo += b0; hi += b1;
            if (RELU) { lo = fmaxf(lo, 0.0f); hi = fmaxf(hi, 0.0f); }
            op0[j] = lo;
            op1[j] = hi;
        }
    }
}

// ---------------------------------------------------------------------------
// Scalar conv (kept only for dp4: 5 output channels). Runtime Cin, raw weights.
// ---------------------------------------------------------------------------
template <int K, int ROWS, int PXB, int OCB, bool RELU>
__global__ void __launch_bounds__(ROWS * HW / PXB)
conv2(const float* __restrict__ in, const float* __restrict__ wt,
      const float* __restrict__ bias, float* __restrict__ out,
      int Cin, int Cout, int nb) {
    constexpr int KK   = K * K;
    constexpr int PAD  = K / 2;
    constexpr int TW   = HW + K - 1;
    constexpr int TH   = ROWS + K - 1;
    constexpr int NTHR = ROWS * HW / PXB;
    constexpr int RPT  = HW / PXB;

    __shared__ float s_in[TH * TW];
    __shared__ float s_w[KK * OCB];

    const int tid    = threadIdx.x;
    const int bIn    = blockIdx.x % nb;
    const int ocBase = blockIdx.y * OCB;
    const int row0   = blockIdx.z * ROWS;

    float acc[OCB][PXB];
#pragma unroll
    for (int o = 0; o < OCB; o++)
#pragma unroll
        for (int j = 0; j < PXB; j++) acc[o][j] = 0.0f;

    const int r    = tid / RPT;
    const int col0 = (tid % RPT) * PXB;
    const float* inB = in + (size_t)bIn * Cin * NPX;

    for (int c = 0; c < Cin; c++) {
        __syncthreads();
        const float* ip = inB + (size_t)c * NPX;
        for (int idx = tid; idx < TH * TW; idx += NTHR) {
            int ty = idx / TW, tx = idx % TW;
            int gy = row0 + ty - PAD, gx = tx - PAD;
            float v = 0.0f;
            if (gy >= 0 && gy < HW && gx >= 0 && gx < HW) v = ip[gy * HW + gx];
            s_in[idx] = v;
        }
        for (int idx = tid; idx < KK * OCB; idx += NTHR) {
            int kk = idx / OCB, o = idx % OCB;
            s_w[idx] = wt[((size_t)(ocBase + o) * Cin + c) * KK + kk];
        }
        __syncthreads();

        const float* pv = s_in + r * TW + col0;
#pragma unroll
        for (int kk = 0; kk < KK; kk++) {
            const int ky = kk / K, kx = kk % K;
            float w[OCB];
#pragma unroll
            for (int o = 0; o < OCB; o++) w[o] = s_w[kk * OCB + o];
            float v[PXB];
#pragma unroll
            for (int j = 0; j < PXB; j++) v[j] = pv[ky * TW + kx + j];
#pragma unroll
            for (int o = 0; o < OCB; o++)
#pragma unroll
                for (int j = 0; j < PXB; j++)
                    acc[o][j] = fmaf(w[o], v[j], acc[o][j]);
        }
    }

#pragma unroll
    for (int o = 0; o < OCB; o++) {
        int oc = ocBase + o;
        float bv = bias[oc];
        float* op = out + ((size_t)blockIdx.x * Cout + oc) * NPX + (row0 + r) * HW + col0;
#pragma unroll
        for (int j = 0; j < PXB; j++) {
            float x = acc[o][j] + bv;
            if (RELU) x = fmaxf(x, 0.0f);
            op[j] = x;
        }
    }
}

// ---------------------------------------------------------------------------
// Generic split-K reduction: out[idx] = relu(bias[oc] + sum_s part[idx+s*tot])
// ---------------------------------------------------------------------------
template <int SPLITS>
__global__ void reduceK(const float* __restrict__ part, const float* __restrict__ bias,
                        float* __restrict__ out, int Cout, int tot) {
    int idx = blockIdx.x * 256 + threadIdx.x;
    if (idx >= tot) return;
    int oc = (idx / NPX) % Cout;
    float v = bias[oc];
#pragma unroll
    for (int s = 0; s < SPLITS; s++) v += part[idx + (size_t)s * tot];
    out[idx] = fmaxf(v, 0.0f);
}

// ---------------------------------------------------------------------------
// Final: disp out, softmax(conf), warp source views, blend.
// ---------------------------------------------------------------------------
__global__ void final_kernel(const float* __restrict__ x, const float* __restrict__ img,
                             const int* __restrict__ ind, float* __restrict__ out) {
    int t = blockIdx.x;  // 0..24
    float t_h = (float)(t / 5), t_w = (float)(t % 5);
    const float* base = x + t * 5 * NPX;
    const float sc = 48.0f / 47.0f;
    for (int p = threadIdx.x; p < NPX; p += blockDim.x) {
        float d0 = base[p];
        float l0 = base[1 * NPX + p];
        float l1 = base[2 * NPX + p];
        float l2 = base[3 * NPX + p];
        float l3 = base[4 * NPX + p];
        float m = fmaxf(fmaxf(l0, l1), fmaxf(l2, l3));
        float e0 = expf(l0 - m), e1 = expf(l1 - m), e2 = expf(l2 - m), e3 = expf(l3 - m);
        float inv = 1.0f / (e0 + e1 + e2 + e3);
        float conf[4] = {e0 * inv, e1 * inv, e2 * inv, e3 * inv};

        int y = p / HW, xx = p % HW;
        float accv = 0.0f;
#pragma unroll
        for (int s = 0; s < 4; s++) {
            int is = ind[s];
            float dw = t_w - (float)(is % 5);
            float dh = t_h - (float)(is / 5);
            float ix = ((float)xx + d0 * dw) * sc - 0.5f;
            float iy = ((float)y  + d0 * dh) * sc - 0.5f;
            accv += conf[s] * bilin48(img + s * NPX, ix, iy);
        }
        out[t * NPX + p]            = d0;    // disp_target
        out[25 * NPX + t * NPX + p] = accv;  // inter_lf
    }
}

// ---------------------------------------------------------------------------
// Launch
// ---------------------------------------------------------------------------
extern "C" void kernel_launch(void* const* d_in, const int* in_sizes, int n_in,
                              void* d_out, int out_size) {
    const float* img = (const float*)d_in[0];
    const int*   ind = (const int*)d_in[1];
    const float* pp1_w = (const float*)d_in[2];  const float* pp1_b = (const float*)d_in[3];
    const float* pp2_w = (const float*)d_in[4];  const float* pp2_b = (const float*)d_in[5];
    const float* pp3_w = (const float*)d_in[6];  const float* pp3_b = (const float*)d_in[7];
    const float* pp4_w = (const float*)d_in[8];  const float* pp4_b = (const float*)d_in[9];
    const float* cp1_w = (const float*)d_in[10]; const float* cp1_b = (const float*)d_in[11];
    const float* cp2_w = (const float*)d_in[12]; const float* cp2_b = (const float*)d_in[13];
    const float* cp3_w = (const float*)d_in[14]; const float* cp3_b = (const float*)d_in[15];
    const float* dp1_w = (const float*)d_in[16]; const float* dp1_b = (const float*)d_in[17];
    const float* dp2_w = (const float*)d_in[18]; const float* dp2_b = (const float*)d_in[19];
    const float* dp3_w = (const float*)d_in[20]; const float* dp3_b = (const float*)d_in[21];
    const float* dp4_w = (const float*)d_in[22]; const float* dp4_b = (const float*)d_in[23];

    float* bufA;  cudaGetSymbolAddress((void**)&bufA, g_bufA);
    float* bufB;  cudaGetSymbolAddress((void**)&bufB, g_bufB);
    float* wT;    cudaGetSymbolAddress((void**)&wT,   g_wT);
    float* part = bufB + (size_t)25 * 8 * NPX;   // cp3 partials (10 slices, 4.6M)

    // 0) transpose all convp weights -> g_wT ([cin][tap][oc] per layer)
    wtransAll<<<dim3(176, 10), 256>>>(pp1_w, pp2_w, pp3_w, pp4_w, cp1_w, cp2_w,
                                      cp3_w, dp1_w, dp2_w, dp3_w, wT);

    // 1) PSV sampling -> bufA [200, 4, 48, 48]
    psv_kernel<<<800, 256>>>(img, ind, bufA);

    // 2) pp chain (batch 200) — PXB=4, 192-thread blocks
    convp<5, 16, 4, 8, 4,   1, true><<<dim3(200, 4, 3), 192>>>(bufA, wT + 0,      pp1_b, bufB, 32, 200);
    convp<5, 16, 4, 8, 32,  1, true><<<dim3(200, 8, 3), 192>>>(bufB, wT + 3200,   pp2_b, bufA, 64, 200);
    convp<5, 16, 4, 8, 64,  1, true><<<dim3(200, 4, 3), 192>>>(bufA, wT + 54400,  pp3_b, bufB, 32, 200);
    convp<5, 16, 4, 4, 32,  1, true><<<dim3(200, 1, 3), 192>>>(bufB, wT + 105600, pp4_b, bufA, 4,  200);

    // bufA reinterpreted as [25, 32, 48, 48]
    // 3) cp chain (batch 25)
    convp<3, 16, 4, 8, 32,  1, true><<<dim3(25, 25, 3), 192>>>(bufA, wT + 108800, cp1_b, bufB, 200, 25);
    convp<3, 16, 4, 8, 200, 1, true><<<dim3(25, 25, 3), 192>>>(bufB, wT + 166400, cp2_b, bufA, 200, 25);
    // cp3: 200->8, split-K 10 -> grid (250,1,3) = 750 blocks
    convp<5, 16, 4, 8, 20, 10, false><<<dim3(250, 1, 3), 192>>>(bufA, wT + 526400, cp3_b, part, 8, 25);
    reduceK<10><<<25 * 8 * NPX / 256, 256>>>(part, cp3_b, bufB, 8, 25 * 8 * NPX);

    // 4) dp chain (batch 25)
    convp<5, 16, 4, 8, 8,   1, true><<<dim3(25, 8, 3), 192>>>(bufB, wT + 566400, dp1_b, bufA, 64, 25);
    convp<5, 16, 4, 8, 64,  1, true><<<dim3(25, 4, 3), 192>>>(bufA, wT + 579200, dp2_b, bufB, 32, 25);
    convp<3, 16, 4, 8, 32,  1, true><<<dim3(25, 2, 3), 192>>>(bufB, wT + 630400, dp3_b, bufA, 16, 25);
    conv2<3, 8, 6, 5, false><<<dim3(25, 1, 6), 64>>>(bufA, dp4_w, dp4_b, bufB, 16, 5, 25);

    // 5) disp + softmax-blended warp -> d_out [disp(57600) | inter_lf(57600)]
    final_kernel<<<25, 256>>>(bufB, img, ind, (float*)d_out);
}

// round 17
// speedup vs baseline: 1.1667x; 1.1639x over previous
#include <cuda_runtime.h>
#include <cuda_bf16.h>
#include <math.h>
#include <stdint.h>

// ---------------------------------------------------------------------------
// Problem constants (N=1, S=4, AN=5 -> an2=25, D=8, H=W=48, PSV_RANGE=4)
// ---------------------------------------------------------------------------
#define HW 48
#define NPX (HW * HW)          // 2304

// Ping-pong scratch: max tensor is pp2 output [200, 64, 48, 48]
__device__ float g_bufA[200 * 64 * NPX];
__device__ float g_bufB[200 * 64 * NPX];
__device__ float g_wT[640000];   // transposed weights, all conv layers

// ---------------------------------------------------------------------------
// Packed-fp32 + async-copy helpers
// ---------------------------------------------------------------------------
__device__ __forceinline__ uint32_t smem_u32(const void* p) {
    uint32_t a;
    asm("{ .reg .u64 t; cvta.to.shared.u64 t, %1; cvt.u32.u64 %0, t; }"
        : "=r"(a) : "l"(p));
    return a;
}
__device__ __forceinline__ void lds128v2(uint32_t addr,
                                         unsigned long long& a, unsigned long long& b) {
    asm volatile("ld.shared.v2.b64 {%0, %1}, [%2];" : "=l"(a), "=l"(b) : "r"(addr));
}
__device__ __forceinline__ unsigned long long bcast2(float v) {
    unsigned long long r;
    asm("mov.b64 %0, {%1, %1};" : "=l"(r) : "f"(v));
    return r;
}
__device__ __forceinline__ void ffma2(unsigned long long& d,
                                      unsigned long long a, unsigned long long b) {
    asm("fma.rn.f32x2 %0, %1, %2, %0;" : "+l"(d) : "l"(a), "l"(b));
}
__device__ __forceinline__ void unpack2(unsigned long long p, float& lo, float& hi) {
    asm("mov.b64 {%0, %1}, %2;" : "=f"(lo), "=f"(hi) : "l"(p));
}
__device__ __forceinline__ void cp_async8(uint32_t dst, const void* src) {
    asm volatile("cp.async.ca.shared.global [%0], [%1], 8;" :: "r"(dst), "l"(src));
}
__device__ __forceinline__ void cp_async16(uint32_t dst, const void* src) {
    asm volatile("cp.async.ca.shared.global [%0], [%1], 16;" :: "r"(dst), "l"(src));
}
__device__ __forceinline__ void cp_commit() {
    asm volatile("cp.async.commit_group;");
}
__device__ __forceinline__ void cp_wait0() {
    asm volatile("cp.async.wait_group 0;");
}

// ---------------------------------------------------------------------------
// Weight transpose: [Cout][Cin][KK] -> [Cin*KK][Cout] per layer (g_wT offsets)
// ---------------------------------------------------------------------------
__global__ void wtransAll(const float* w0, const float* w1, const float* w2,
                          const float* w3, const float* w4, const float* w5,
                          const float* w6, const float* w7, const float* w8,
                          const float* w9, float* out) {
    int L = blockIdx.y;
    const float* w; int Cout, Cin, KK, off;
    switch (L) {
        case 0: w = w0; Cout = 32;  Cin = 4;   KK = 25; off = 0;      break;
        case 1: w = w1; Cout = 64;  Cin = 32;  KK = 25; off = 3200;   break;
        case 2: w = w2; Cout = 32;  Cin = 64;  KK = 25; off = 54400;  break;
        case 3: w = w3; Cout = 4;   Cin = 32;  KK = 25; off = 105600; break;
        case 4: w = w4; Cout = 200; Cin = 32;  KK = 9;  off = 108800; break;
        case 5: w = w5; Cout = 200; Cin = 200; KK = 9;  off = 166400; break;
        case 6: w = w6; Cout = 8;   Cin = 200; KK = 25; off = 526400; break;
        case 7: w = w7; Cout = 64;  Cin = 8;   KK = 25; off = 566400; break;
        case 8: w = w8; Cout = 32;  Cin = 64;  KK = 25; off = 579200; break;
        default: w = w9; Cout = 16; Cin = 32;  KK = 9;  off = 630400; break;
    }
    int n = Cout * Cin * KK;
    int ck = Cin * KK;
    for (int idx = blockIdx.x * 256 + threadIdx.x; idx < n; idx += gridDim.x * 256) {
        int o = idx / ck, rm = idx % ck;
        int c = rm / KK, k = rm % KK;
        out[off + (c * KK + k) * Cout + o] = w[idx];
    }
}

// ---------------------------------------------------------------------------
// Bilinear sampling identical to reference grid_sample(align_corners=False,
// padding=zeros):  ix = (X+off)*48/47 - 0.5
// ---------------------------------------------------------------------------
__device__ __forceinline__ float tap48(const float* __restrict__ im, int x, int y) {
    return (x >= 0 && x < HW && y >= 0 && y < HW) ? im[y * HW + x] : 0.0f;
}

__device__ __forceinline__ float bilin48(const float* __restrict__ im, float ix, float iy) {
    float x0f = floorf(ix), y0f = floorf(iy);
    int   x0  = (int)x0f,   y0  = (int)y0f;
    float wx = ix - x0f, wy = iy - y0f;
    float v00 = tap48(im, x0,     y0);
    float v01 = tap48(im, x0 + 1, y0);
    float v10 = tap48(im, x0,     y0 + 1);
    float v11 = tap48(im, x0 + 1, y0 + 1);
    return (1.0f - wy) * ((1.0f - wx) * v00 + wx * v01) +
           wy          * ((1.0f - wx) * v10 + wx * v11);
}

// ---------------------------------------------------------------------------
// PSV build: 800 blocks, one per (t,d,s) tuple. Output [td(200), s(4), 2304].
// ---------------------------------------------------------------------------
__global__ void psv_kernel(const float* __restrict__ img, const int* __restrict__ ind,
                           float* __restrict__ out) {
    int k  = blockIdx.x;     // k = (t*8+d)*4 + s
    int s  = k & 3;
    int td = k >> 2;
    int d  = td & 7;
    int t  = td >> 3;
    float t_h = (float)(t / 5), t_w = (float)(t % 5);
    int   is  = ind[s];
    float s_h = (float)(is / 5), s_w = (float)(is % 5);
    float disp = -4.0f + (float)d * (8.0f / 7.0f);  // linspace(-4,4,8)
    float offw = disp * (t_w - s_w);
    float offh = disp * (t_h - s_h);
    const float* im = img + s * NPX;
    float* op = out + (td * 4 + s) * NPX;
    const float sc = 48.0f / 47.0f;
    for (int p = threadIdx.x; p < NPX; p += blockDim.x) {
        int y = p / HW, x = p % HW;
        float ix = ((float)x + offw) * sc - 0.5f;
        float iy = ((float)y + offh) * sc - 0.5f;
        op[p] = bilin48(im, ix, iy);
    }
}

// ---------------------------------------------------------------------------
// Packed-f32x2 direct conv, cp.async pipeline over CHANNEL PAIRS.
// Round-13 optimum: PXB=6, 128-thread blocks, 5 blocks/SM.
//  - tile AND weights both arrive via cp.async (weights from the transposed
//    [cin][tap][oc] copy) -> no register staging, no STS in the mainloop.
//  - padded tile [(ROWS+4) x 52], interior at (2,2); halos zeroed once.
//  - weight fragment = ld.shared.v2.b64 (one LDS.128 -> two f32x2 operands).
//  - per ky: bcast-pack the (K+PXB-1)-value pixel row once, reuse across kx.
// CIN must be even. SPLITS>1: split-K over input channels, raw partials,
// blockIdx.x = slice*nb + b; reduceK combines slices deterministically.
// ---------------------------------------------------------------------------
template <int K, int ROWS, int PXB, int OCB, int CIN, int SPLITS, bool RELU>
__global__ void __launch_bounds__(ROWS * HW / PXB, 5)
convp(const float* __restrict__ in, const float* __restrict__ wtT,
      const float* __restrict__ bias, float* __restrict__ out,
      int Cout, int nb) {
    static_assert(CIN % 2 == 0, "CIN must be even");
    static_assert(OCB % 4 == 0 || OCB == 4, "OCB pairs");
    constexpr int KK   = K * K;
    constexpr int PAD  = K / 2;
    constexpr int TWP  = 52;               // padded width
    constexpr int THP  = ROWS + 4;         // padded height
    constexpr int TTP  = THP * TWP;
    constexpr int NTHR = ROWS * HW / PXB;
    constexpr int RPT  = HW / PXB;
    constexpr int OC2  = OCB / 2;
    constexpr int WCH  = KK * OCB;
    constexpr int WCHK = 2 * WCH / 4;      // 16B chunks per channel pair
    constexpr int NWL  = (WCHK + NTHR - 1) / NTHR;
    constexpr int NCH  = THP * 24;         // 8B chunks per channel fill
    constexpr int NCPA = (NCH + NTHR - 1) / NTHR;
    constexpr int VN   = K + PXB - 1;
    constexpr int NPAIR = CIN / 2;
    constexpr int CINTOT = CIN * SPLITS;

    __shared__ __align__(16) float s_in[2][2 * TTP];   // [slot][2 channels]
    __shared__ __align__(16) float s_w[2][2 * WCH];

    const int tid    = threadIdx.x;
    const int bIn    = blockIdx.x % nb;
    const int slice  = blockIdx.x / nb;
    const int ocBase = blockIdx.y * OCB;
    const int row0   = blockIdx.z * ROWS;
    const int cin0   = slice * CIN;

    const int r    = tid / RPT;
    const int col0 = (tid % RPT) * PXB;
    const float* inB = in + ((size_t)bIn * CINTOT + cin0) * NPX;

    const uint32_t sinAddr = smem_u32(&s_in[0][0]);
    const uint32_t wbase   = smem_u32(&s_w[0][0]);

    // ---- zero all tile buffers (halos/OOB rows stay zero forever) ----
    for (int i = tid; i < 4 * TTP; i += NTHR) (&s_in[0][0])[i] = 0.0f;
    __syncthreads();

    // ---- fill one channel's tile interior via cp.async (8B chunks) ----
    auto fill1 = [&](int ch, uint32_t dstB) {
        const float* ip = inB + (size_t)ch * NPX;
#pragma unroll
        for (int l = 0; l < NCPA; l++) {
            int idx = tid + l * NTHR;
            if (idx < NCH) {
                int ty = idx / 24, chk = idx % 24;
                int gy = row0 + ty - 2;
                if (gy >= 0 && gy < HW)
                    cp_async8(dstB + (uint32_t)((ty * TWP + 2 + chk * 2) * 4),
                              ip + gy * HW + chk * 2);
            }
        }
    };
    auto fillPair = [&](int pair, int slot) {
        uint32_t base = sinAddr + (uint32_t)(slot * 2 * TTP) * 4u;
        fill1(2 * pair,     base);
        fill1(2 * pair + 1, base + (uint32_t)TTP * 4u);
    };
    // ---- weights for a channel pair via 16B cp.async from transposed copy
    auto fillW = [&](int pair, int slot) {
#pragma unroll
        for (int l = 0; l < NWL; l++) {
            int idx = tid + l * NTHR;
            if (idx < WCHK) {
                int q  = idx * 4;            // float offset in [c][kk][oc]
                int c  = q / WCH;
                int rm = q % WCH;
                int kk = rm / OCB;
                int oo = rm % OCB;
                const float* src = wtT +
                    ((size_t)(cin0 + 2 * pair + c) * KK + kk) * Cout + ocBase + oo;
                cp_async16(wbase + (uint32_t)((slot * 2 * WCH + q) * 4), src);
            }
        }
    };

    // ---- prestage pair 0 ----
    fillPair(0, 0);
    fillW(0, 0);
    cp_commit();
    cp_wait0();
    __syncthreads();

    unsigned long long acc[OC2][PXB];
#pragma unroll
    for (int o2 = 0; o2 < OC2; o2++)
#pragma unroll
        for (int j = 0; j < PXB; j++) acc[o2][j] = 0ULL;

#pragma unroll 1
    for (int p2 = 0; p2 < NPAIR; p2++) {
        const int slot = p2 & 1;
        if (p2 + 1 < NPAIR) {
            fillPair(p2 + 1, slot ^ 1);
            fillW(p2 + 1, slot ^ 1);
            cp_commit();
        }

        // compute both channels of this pair
#pragma unroll
        for (int sub = 0; sub < 2; sub++) {
            const float* pv = &s_in[slot][sub * TTP + (r + 2 - PAD) * TWP + col0 + 2 - PAD];
            const uint32_t wb = wbase + (uint32_t)((slot * 2 * WCH + sub * WCH) * 4);
#pragma unroll
            for (int ky = 0; ky < K; ky++) {
                unsigned long long vb[VN];
#pragma unroll
                for (int i = 0; i < VN; i++) vb[i] = bcast2(pv[ky * TWP + i]);
#pragma unroll
                for (int kx = 0; kx < K; kx++) {
                    unsigned long long w2[OC2];
#pragma unroll
                    for (int o2 = 0; o2 < OC2; o2 += 2)
                        lds128v2(wb + (uint32_t)(((ky * K + kx) * OCB + 2 * o2) * 4),
                                 w2[o2], w2[o2 + 1]);
#pragma unroll
                    for (int j = 0; j < PXB; j++)
#pragma unroll
                        for (int o2 = 0; o2 < OC2; o2++)
                            ffma2(acc[o2][j], w2[o2], vb[kx + j]);
                }
            }
        }

        if (p2 + 1 < NPAIR) cp_wait0();
        __syncthreads();
    }

    // ---- epilogue: unpack pairs, bias, relu, store ----
#pragma unroll
    for (int o2 = 0; o2 < OC2; o2++) {
        int oc0 = ocBase + 2 * o2;
        float b0 = (SPLITS == 1) ? bias[oc0]     : 0.0f;
        float b1 = (SPLITS == 1) ? bias[oc0 + 1] : 0.0f;
        float* op0 = out + ((size_t)blockIdx.x * Cout + oc0) * NPX + (row0 + r) * HW + col0;
        float* op1 = op0 + NPX;
#pragma unroll
        for (int j = 0; j < PXB; j++) {
            float lo, hi;
            unpack2(acc[o2][j], lo, hi);
            lo += b0; hi += b1;
            if (RELU) { lo = fmaxf(lo, 0.0f); hi = fmaxf(hi, 0.0f); }
            op0[j] = lo;
            op1[j] = hi;
        }
    }
}

// ---------------------------------------------------------------------------
// Scalar conv (kept only for dp4: 5 output channels). Runtime Cin, raw weights.
// ---------------------------------------------------------------------------
template <int K, int ROWS, int PXB, int OCB, bool RELU>
__global__ void __launch_bounds__(ROWS * HW / PXB)
conv2(const float* __restrict__ in, const float* __restrict__ wt,
      const float* __restrict__ bias, float* __restrict__ out,
      int Cin, int Cout, int nb) {
    constexpr int KK   = K * K;
    constexpr int PAD  = K / 2;
    constexpr int TW   = HW + K - 1;
    constexpr int TH   = ROWS + K - 1;
    constexpr int NTHR = ROWS * HW / PXB;
    constexpr int RPT  = HW / PXB;

    __shared__ float s_in[TH * TW];
    __shared__ float s_w[KK * OCB];

    const int tid    = threadIdx.x;
    const int bIn    = blockIdx.x % nb;
    const int ocBase = blockIdx.y * OCB;
    const int row0   = blockIdx.z * ROWS;

    float acc[OCB][PXB];
#pragma unroll
    for (int o = 0; o < OCB; o++)
#pragma unroll
        for (int j = 0; j < PXB; j++) acc[o][j] = 0.0f;

    const int r    = tid / RPT;
    const int col0 = (tid % RPT) * PXB;
    const float* inB = in + (size_t)bIn * Cin * NPX;

    for (int c = 0; c < Cin; c++) {
        __syncthreads();
        const float* ip = inB + (size_t)c * NPX;
        for (int idx = tid; idx < TH * TW; idx += NTHR) {
            int ty = idx / TW, tx = idx % TW;
            int gy = row0 + ty - PAD, gx = tx - PAD;
            float v = 0.0f;
            if (gy >= 0 && gy < HW && gx >= 0 && gx < HW) v = ip[gy * HW + gx];
            s_in[idx] = v;
        }
        for (int idx = tid; idx < KK * OCB; idx += NTHR) {
            int kk = idx / OCB, o = idx % OCB;
            s_w[idx] = wt[((size_t)(ocBase + o) * Cin + c) * KK + kk];
        }
        __syncthreads();

        const float* pv = s_in + r * TW + col0;
#pragma unroll
        for (int kk = 0; kk < KK; kk++) {
            const int ky = kk / K, kx = kk % K;
            float w[OCB];
#pragma unroll
            for (int o = 0; o < OCB; o++) w[o] = s_w[kk * OCB + o];
            float v[PXB];
#pragma unroll
            for (int j = 0; j < PXB; j++) v[j] = pv[ky * TW + kx + j];
#pragma unroll
            for (int o = 0; o < OCB; o++)
#pragma unroll
                for (int j = 0; j < PXB; j++)
                    acc[o][j] = fmaf(w[o], v[j], acc[o][j]);
        }
    }

#pragma unroll
    for (int o = 0; o < OCB; o++) {
        int oc = ocBase + o;
        float bv = bias[oc];
        float* op = out + ((size_t)blockIdx.x * Cout + oc) * NPX + (row0 + r) * HW + col0;
#pragma unroll
        for (int j = 0; j < PXB; j++) {
            float x = acc[o][j] + bv;
            if (RELU) x = fmaxf(x, 0.0f);
            op[j] = x;
        }
    }
}

// ---------------------------------------------------------------------------
// Generic split-K reduction: out[idx] = relu(bias[oc] + sum_s part[idx+s*tot])
// ---------------------------------------------------------------------------
template <int SPLITS>
__global__ void reduceK(const float* __restrict__ part, const float* __restrict__ bias,
                        float* __restrict__ out, int Cout, int tot) {
    int idx = blockIdx.x * 256 + threadIdx.x;
    if (idx >= tot) return;
    int oc = (idx / NPX) % Cout;
    float v = bias[oc];
#pragma unroll
    for (int s = 0; s < SPLITS; s++) v += part[idx + (size_t)s * tot];
    out[idx] = fmaxf(v, 0.0f);
}

// ---------------------------------------------------------------------------
// Final: disp out, softmax(conf), warp source views, blend.
// ---------------------------------------------------------------------------
__global__ void final_kernel(const float* __restrict__ x, const float* __restrict__ img,
                             const int* __restrict__ ind, float* __restrict__ out) {
    int t = blockIdx.x;  // 0..24
    float t_h = (float)(t / 5), t_w = (float)(t % 5);
    const float* base = x + t * 5 * NPX;
    const float sc = 48.0f / 47.0f;
    for (int p = threadIdx.x; p < NPX; p += blockDim.x) {
        float d0 = base[p];
        float l0 = base[1 * NPX + p];
        float l1 = base[2 * NPX + p];
        float l2 = base[3 * NPX + p];
        float l3 = base[4 * NPX + p];
        float m = fmaxf(fmaxf(l0, l1), fmaxf(l2, l3));
        float e0 = expf(l0 - m), e1 = expf(l1 - m), e2 = expf(l2 - m), e3 = expf(l3 - m);
        float inv = 1.0f / (e0 + e1 + e2 + e3);
        float conf[4] = {e0 * inv, e1 * inv, e2 * inv, e3 * inv};

        int y = p / HW, xx = p % HW;
        float accv = 0.0f;
#pragma unroll
        for (int s = 0; s < 4; s++) {
            int is = ind[s];
            float dw = t_w - (float)(is % 5);
            float dh = t_h - (float)(is / 5);
            float ix = ((float)xx + d0 * dw) * sc - 0.5f;
            float iy = ((float)y  + d0 * dh) * sc - 0.5f;
            accv += conf[s] * bilin48(img + s * NPX, ix, iy);
        }
        out[t * NPX + p]            = d0;    // disp_target
        out[25 * NPX + t * NPX + p] = accv;  // inter_lf
    }
}

// ---------------------------------------------------------------------------
// Launch (round-13 geometry; only dp2 changed: OCB 8->4, grid (25,8,3))
// ---------------------------------------------------------------------------
extern "C" void kernel_launch(void* const* d_in, const int* in_sizes, int n_in,
                              void* d_out, int out_size) {
    const float* img = (const float*)d_in[0];
    const int*   ind = (const int*)d_in[1];
    const float* pp1_w = (const float*)d_in[2];  const float* pp1_b = (const float*)d_in[3];
    const float* pp2_w = (const float*)d_in[4];  const float* pp2_b = (const float*)d_in[5];
    const float* pp3_w = (const float*)d_in[6];  const float* pp3_b = (const float*)d_in[7];
    const float* pp4_w = (const float*)d_in[8];  const float* pp4_b = (const float*)d_in[9];
    const float* cp1_w = (const float*)d_in[10]; const float* cp1_b = (const float*)d_in[11];
    const float* cp2_w = (const float*)d_in[12]; const float* cp2_b = (const float*)d_in[13];
    const float* cp3_w = (const float*)d_in[14]; const float* cp3_b = (const float*)d_in[15];
    const float* dp1_w = (const float*)d_in[16]; const float* dp1_b = (const float*)d_in[17];
    const float* dp2_w = (const float*)d_in[18]; const float* dp2_b = (const float*)d_in[19];
    const float* dp3_w = (const float*)d_in[20]; const float* dp3_b = (const float*)d_in[21];
    const float* dp4_w = (const float*)d_in[22]; const float* dp4_b = (const float*)d_in[23];

    float* bufA;  cudaGetSymbolAddress((void**)&bufA, g_bufA);
    float* bufB;  cudaGetSymbolAddress((void**)&bufB, g_bufB);
    float* wT;    cudaGetSymbolAddress((void**)&wT,   g_wT);
    float* part = bufB + (size_t)25 * 8 * NPX;   // cp3 partials (10 slices, 4.6M)

    // 0) transpose all convp weights -> g_wT ([cin][tap][oc] per layer)
    wtransAll<<<dim3(176, 10), 256>>>(pp1_w, pp2_w, pp3_w, pp4_w, cp1_w, cp2_w,
                                      cp3_w, dp1_w, dp2_w, dp3_w, wT);

    // 1) PSV sampling -> bufA [200, 4, 48, 48]
    psv_kernel<<<800, 256>>>(img, ind, bufA);

    // 2) pp chain (batch 200)
    convp<5, 16, 6, 8, 4,   1, true><<<dim3(200, 4, 3), 128>>>(bufA, wT + 0,      pp1_b, bufB, 32, 200);
    convp<5, 16, 6, 8, 32,  1, true><<<dim3(200, 8, 3), 128>>>(bufB, wT + 3200,   pp2_b, bufA, 64, 200);
    convp<5, 16, 6, 8, 64,  1, true><<<dim3(200, 4, 3), 128>>>(bufA, wT + 54400,  pp3_b, bufB, 32, 200);
    convp<5, 16, 6, 4, 32,  1, true><<<dim3(200, 1, 3), 128>>>(bufB, wT + 105600, pp4_b, bufA, 4,  200);

    // bufA reinterpreted as [25, 32, 48, 48]
    // 3) cp chain (batch 25)
    convp<3, 16, 6, 8, 32,  1, true><<<dim3(25, 25, 3), 128>>>(bufA, wT + 108800, cp1_b, bufB, 200, 25);
    convp<3, 16, 6, 8, 200, 1, true><<<dim3(25, 25, 3), 128>>>(bufB, wT + 166400, cp2_b, bufA, 200, 25);
    // cp3: 200->8, split-K 10 -> grid (250,1,3) = 750 blocks
    convp<5, 16, 6, 8, 20, 10, false><<<dim3(250, 1, 3), 128>>>(bufA, wT + 526400, cp3_b, part, 8, 25);
    reduceK<10><<<25 * 8 * NPX / 256, 256>>>(part, cp3_b, bufB, 8, 25 * 8 * NPX);

    // 4) dp chain (batch 25)
    convp<5, 16, 6, 8, 8,   1, true><<<dim3(25, 8, 3), 128>>>(bufB, wT + 566400, dp1_b, bufA, 64, 25);
    // dp2: OCB=4 -> grid 600 blocks (0.81 waves vs 0.41 at OCB=8)
    convp<5, 16, 6, 4, 64,  1, true><<<dim3(25, 8, 3), 128>>>(bufA, wT + 579200, dp2_b, bufB, 32, 25);
    convp<3, 8,  6, 8, 32,  1, true><<<dim3(25, 2, 6), 64>>>(bufB, wT + 630400, dp3_b, bufA, 16, 25);
    conv2<3, 8, 6, 5, false><<<dim3(25, 1, 6), 64>>>(bufA, dp4_w, dp4_b, bufB, 16, 5, 25);

    // 5) disp + softmax-blended warp -> d_out [disp(57600) | inter_lf(57600)]
    final_kernel<<<25, 256>>>(bufB, img, ind, (float*)d_out);
}